// round 17
// baseline (speedup 1.0000x reference)
#include <cuda_runtime.h>
#include <cuda_fp16.h>
#include <stdint.h>

// ---------------------------------------------------------------------------
// StyleGAN2 modulated 3x3 conv, NHWC, N=16 H=W=64 C=O=512
// Round 17: conv = R11/R16 verbatim (857us measured; frozen).
//           prep_a latency attack: style MLP 16 (8 accs), ssq MLP 9
//           (batch loads then FMA tree). prep_b: dmul 8 accs, xsplit
//           8 elems/thread.
// ---------------------------------------------------------------------------

#define NN 16
#define HH 64
#define WW 64
#define CC 512
#define OO 512
#define NWD 14

#define A_BYTES 33792        // 264 halo rows x 128B  (4x66 spatial, kc=64)
#define OFF_B0  67584        // after 2 A buffers
#define B_BYTES 16384        // 128 o-rows x 128B
#define SMEM_TOTAL (OFF_B0 + 2 * B_BYTES)   // 100352
#define NCHUNK 72            // 9 taps x 8 c-chunks

// ---- device scratch (allocation-free) --------------------------------------
__device__ float g_s[NN * CC];
__device__ float g_dmul[NN * OO];
__device__ float g_ssq[CC * OO];
__device__ __half g_xh[NN * HH * WW * CC];   // fp16(x*s)
__device__ __half g_wt[9 * OO * CC];         // fp16 w^T [tap][o][c]

// ---- helpers -----------------------------------------------------------------
static __device__ __forceinline__ uint32_t smem_u32(const void* p) {
    uint32_t a;
    asm("{ .reg .u64 t; cvta.to.shared.u64 t, %1; cvt.u32.u64 %0, t; }"
        : "=r"(a) : "l"(p));
    return a;
}

#define CP16(dst, src, sz)                                                   \
    asm volatile("cp.async.cg.shared.global [%0], [%1], 16, %2;"             \
                 :: "r"(dst), "l"(src), "r"(sz) : "memory")
#define CP_COMMIT() asm volatile("cp.async.commit_group;" ::: "memory")
#define CP_WAIT0()  asm volatile("cp.async.wait_group 0;" ::: "memory")

#define LDSM4(r, addr)                                                       \
    asm volatile("ldmatrix.sync.aligned.m8n8.x4.shared.b16 "                 \
                 "{%0,%1,%2,%3}, [%4];"                                      \
                 : "=r"((r)[0]), "=r"((r)[1]), "=r"((r)[2]), "=r"((r)[3])    \
                 : "r"(addr))

#define MMA2(d, a, b0, b1)                                                   \
    asm volatile("mma.sync.aligned.m16n8k16.row.col.f32.f16.f16.f32 "        \
                 "{%0,%1,%2,%3}, {%4,%5,%6,%7}, {%8,%9}, {%0,%1,%2,%3};"     \
                 : "+f"((d)[0]), "+f"((d)[1]), "+f"((d)[2]), "+f"((d)[3])    \
                 : "r"((a)[0]), "r"((a)[1]), "r"((a)[2]), "r"((a)[3]),       \
                   "r"(b0), "r"(b1))

// ---- prep_a: style (0..15) | ssq (16..527) | w transpose fp16 (528..1679) -------
__global__ void prep_a_kernel(const float* __restrict__ dlat,
                              const float* __restrict__ sw,
                              const float* __restrict__ sb,
                              const int*   __restrict__ lidx,
                              const float* __restrict__ weight)
{
    int bid = blockIdx.x;
    int tid = threadIdx.x;
    if (bid < NN) {
        int n = bid;
        __shared__ float dl[CC];
        int li = *lidx;
        dl[tid] = dlat[(n * NWD + li) * CC + tid];
        __syncthreads();
        float a0 = 0.f, a1 = 0.f, a2 = 0.f, a3 = 0.f;
        float a4 = 0.f, a5 = 0.f, a6 = 0.f, a7 = 0.f;
#pragma unroll 2
        for (int w = 0; w < CC; w += 8) {
            float v0 = sw[(w)     * CC + tid];
            float v1 = sw[(w + 1) * CC + tid];
            float v2 = sw[(w + 2) * CC + tid];
            float v3 = sw[(w + 3) * CC + tid];
            float v4 = sw[(w + 4) * CC + tid];
            float v5 = sw[(w + 5) * CC + tid];
            float v6 = sw[(w + 6) * CC + tid];
            float v7 = sw[(w + 7) * CC + tid];
            a0 = fmaf(dl[w],     v0, a0);
            a1 = fmaf(dl[w + 1], v1, a1);
            a2 = fmaf(dl[w + 2], v2, a2);
            a3 = fmaf(dl[w + 3], v3, a3);
            a4 = fmaf(dl[w + 4], v4, a4);
            a5 = fmaf(dl[w + 5], v5, a5);
            a6 = fmaf(dl[w + 6], v6, a6);
            a7 = fmaf(dl[w + 7], v7, a7);
        }
        float acc = ((a0 + a1) + (a2 + a3)) + ((a4 + a5) + (a6 + a7));
        g_s[n * CC + tid] = acc * 0.044194173824159216f + sb[tid];
    } else if (bid < NN + CC) {
        int i = bid - NN;
        float v[9];
#pragma unroll
        for (int tp = 0; tp < 9; ++tp)
            v[tp] = weight[(tp * CC + i) * OO + tid];
        float s0 = fmaf(v[0], v[0], v[1] * v[1]);
        float s1 = fmaf(v[2], v[2], v[3] * v[3]);
        float s2 = fmaf(v[4], v[4], v[5] * v[5]);
        float s3 = fmaf(v[6], v[6], v[7] * v[7]);
        g_ssq[i * OO + tid] = ((s0 + s1) + (s2 + s3)) + v[8] * v[8];
    } else {
        __shared__ float ts[2][32][33];
        int sub = tid >> 8;
        int st  = tid & 255;
        int wb  = (bid - (NN + CC)) * 2 + sub;   // 0..2303
        int tap = wb >> 8;
        int rem = wb & 255;
        int o0 = (rem & 15) * 32;
        int c0 = (rem >> 4) * 32;
        int tx = st & 31, ty = st >> 5;
#pragma unroll
        for (int j = 0; j < 32; j += 8)
            ts[sub][j + ty][tx] = weight[(tap * CC + c0 + j + ty) * OO + o0 + tx];
        __syncthreads();
#pragma unroll
        for (int j = 0; j < 32; j += 8) {
            float v = ts[sub][tx][j + ty];
            int oi = (tap * OO + o0 + j + ty) * CC + c0 + tx;
            g_wt[oi] = __float2half_rn(v);
        }
    }
}

// ---- prep_b: dmul (blocks 0..15) | xsplit fp16 (rest, 8 elems/thread) -----------
__global__ void prep_b_kernel(const float* __restrict__ x)
{
    int bid = blockIdx.x;
    int tid = threadIdx.x;
    if (bid < NN) {
        int n = bid;
        int o = tid;
        __shared__ float s2[CC];
        float sv = g_s[n * CC + o];
        s2[o] = sv * sv;
        __syncthreads();
        float a0 = 0.f, a1 = 0.f, a2 = 0.f, a3 = 0.f;
        float a4 = 0.f, a5 = 0.f, a6 = 0.f, a7 = 0.f;
#pragma unroll 2
        for (int i = 0; i < CC; i += 8) {
            float v0 = g_ssq[(i)     * OO + o];
            float v1 = g_ssq[(i + 1) * OO + o];
            float v2 = g_ssq[(i + 2) * OO + o];
            float v3 = g_ssq[(i + 3) * OO + o];
            float v4 = g_ssq[(i + 4) * OO + o];
            float v5 = g_ssq[(i + 5) * OO + o];
            float v6 = g_ssq[(i + 6) * OO + o];
            float v7 = g_ssq[(i + 7) * OO + o];
            a0 = fmaf(s2[i],     v0, a0);
            a1 = fmaf(s2[i + 1], v1, a1);
            a2 = fmaf(s2[i + 2], v2, a2);
            a3 = fmaf(s2[i + 3], v3, a3);
            a4 = fmaf(s2[i + 4], v4, a4);
            a5 = fmaf(s2[i + 5], v5, a5);
            a6 = fmaf(s2[i + 6], v6, a6);
            a7 = fmaf(s2[i + 7], v7, a7);
        }
        float acc = ((a0 + a1) + (a2 + a3)) + ((a4 + a5) + (a6 + a7));
        const float ws2 = 1.0f / 4608.0f;
        const float ws  = 0.014731391274719738f;
        g_dmul[n * OO + o] = ws * rsqrtf(ws2 * acc + 1e-8f);
    } else {
        int t = (bid - NN) * 512 + tid;
        int e = t * 8;
        int c = e & (CC - 1);
        int n = e >> 21;
        const float4* xp = (const float4*)(x + e);
        const float4* sp = (const float4*)(g_s + n * CC + c);
        float4 v0 = xp[0], v1 = xp[1];
        float4 s0 = sp[0], s1 = sp[1];
        __half h0 = __float2half_rn(v0.x * s0.x);
        __half h1 = __float2half_rn(v0.y * s0.y);
        __half h2 = __float2half_rn(v0.z * s0.z);
        __half h3 = __float2half_rn(v0.w * s0.w);
        __half h4 = __float2half_rn(v1.x * s1.x);
        __half h5 = __float2half_rn(v1.y * s1.y);
        __half h6 = __float2half_rn(v1.z * s1.z);
        __half h7 = __float2half_rn(v1.w * s1.w);
        uint4 ph;
        ph.x = (uint32_t)__half_as_ushort(h0) | ((uint32_t)__half_as_ushort(h1) << 16);
        ph.y = (uint32_t)__half_as_ushort(h2) | ((uint32_t)__half_as_ushort(h3) << 16);
        ph.z = (uint32_t)__half_as_ushort(h4) | ((uint32_t)__half_as_ushort(h5) << 16);
        ph.w = (uint32_t)__half_as_ushort(h6) | ((uint32_t)__half_as_ushort(h7) << 16);
        *(uint4*)(g_xh + e) = ph;
    }
}

// ---- A halo staging: 264 rows (4x66 spatial, zero-padded), kc=64 ----------------
static __device__ __forceinline__ void load_A(uint32_t dst, int c0,
                                              int n, int h0, int tid)
{
#pragma unroll
    for (int it = 0; it < 2; ++it) {
        int row = tid + it * 256;
        if (row < 264) {
            int rr = row >= 198 ? 3 : (row >= 132 ? 2 : (row >= 66 ? 1 : 0));
            int cc = row - rr * 66;
            int h = h0 + rr - 1;
            int w = cc - 1;
            const bool ok = ((unsigned)h < (unsigned)HH) && ((unsigned)w < (unsigned)WW);
            const unsigned sz = ok ? 16u : 0u;
            const size_t gi = ((size_t)((n * HH + (ok ? h : 0)) * WW + (ok ? w : 0)) * CC + c0) * 2;
            const char* src = (const char*)g_xh + gi;
            const int r7 = row & 7;
            const uint32_t rbase = dst + (uint32_t)row * 128u;
#pragma unroll
            for (int c = 0; c < 8; ++c)
                CP16(rbase + ((c ^ r7) << 4), src + c * 16, sz);
        }
    }
}

// ---- B staging: 128 o-rows x kc=64 ------------------------------------------------
static __device__ __forceinline__ void load_B(uint32_t dst, int tap, int c0,
                                               int o0, int tid)
{
    const int r  = tid >> 1;
    const int cb = (tid & 1) * 4;
    const int r7 = r & 7;
    const size_t bidx = ((size_t)((tap * OO + o0 + r) * CC) + c0 + cb * 8) * 2;
    const char* src = (const char*)g_wt + bidx;
    const uint32_t rbase = dst + (uint32_t)r * 128u;
#pragma unroll
    for (int c = 0; c < 4; ++c)
        CP16(rbase + (((cb + c) ^ r7) << 4), src + c * 16, 16u);
}

// ---- main conv on mma.sync (R11 verbatim; FROZEN) ----------------------------------
__global__ __launch_bounds__(256, 2)
void conv_mma_kernel(const float* __restrict__ bias,
                     const float* __restrict__ nstr,
                     const float* __restrict__ noise,
                     float* __restrict__ out)
{
    extern __shared__ char dynsmem[];
    const uint32_t smbase = smem_u32(dynsmem);

    const int tid  = threadIdx.x;
    const int lane = tid & 31;
    const int wid  = tid >> 5;
    const int wm   = wid & 3;          // M quarter (32 rows)
    const int wn   = wid >> 2;         // N half (64 cols)

    const int o0 = blockIdx.x * 128;
    const int mt = blockIdx.y;
    const int n  = mt >> 5;
    const int h0 = (mt & 31) * 2;

    const int a_row  = wm * 32 + (lane & 15);
    const int a_kh   = lane >> 4;
    const int bg     = lane >> 3;
    const int b_row0 = wn * 64 + ((bg >> 1) << 3) + (lane & 7);
    const int b_kh   = bg & 1;

    const int r0 = a_row,      r1 = a_row + 16;
    const int pb0 = (r0 >> 6) * 66 + (r0 & 63);
    const int pb1 = (r1 >> 6) * 66 + (r1 & 63);

    uint32_t bro[4], br7[4];
#pragma unroll
    for (int nb = 0; nb < 4; ++nb) {
        bro[nb] = (uint32_t)(b_row0 + nb * 16) * 128u;
        br7[nb] = (b_row0 + nb * 16) & 7;
    }

    float acc[2][8][4];
#pragma unroll
    for (int mi = 0; mi < 2; ++mi)
#pragma unroll
        for (int ni = 0; ni < 8; ++ni)
#pragma unroll
            for (int q = 0; q < 4; ++q) acc[mi][ni][q] = 0.f;

    load_A(smbase, 0, n, h0, tid);
    load_B(smbase + OFF_B0, 0, 0, o0, tid);
    CP_COMMIT();

    int tap = 0, k = 0, tapoff = 0;
#pragma unroll 1
    for (int i = 0; i < NCHUNK; ++i) {
        CP_WAIT0();
        __syncthreads();

        if (i + 1 < NCHUNK) {
            int tapj = tap + 1, kj = k;
            if (tapj == 9) { tapj = 0; ++kj; }
            load_B(smbase + OFF_B0 + ((i + 1) & 1) * B_BYTES, tapj, kj * 64, o0, tid);
            if (tap == 3 && k + 1 < 8)
                load_A(smbase + ((k + 1) & 1) * A_BYTES, (k + 1) * 64, n, h0, tid);
        }
        CP_COMMIT();

        const uint32_t sbA = smbase + (k & 1) * A_BYTES;
        const uint32_t sbB = smbase + OFF_B0 + (i & 1) * B_BYTES;
        const int p0 = pb0 + tapoff;
        const int p1 = pb1 + tapoff;
        const uint32_t a0b = sbA + (uint32_t)p0 * 128u;
        const uint32_t a1b = sbA + (uint32_t)p1 * 128u;
        const int p07 = p0 & 7, p17 = p1 & 7;

#pragma unroll
        for (int kk = 0; kk < 4; ++kk) {
            const int rk  = (kk + wid) & 3;
            const int cha = 2 * rk + a_kh;
            const int chb = 2 * rk + b_kh;
            uint32_t aa[2][4], bb[4][4];
            LDSM4(aa[0], a0b + ((cha ^ p07) << 4));
            LDSM4(aa[1], a1b + ((cha ^ p17) << 4));
#pragma unroll
            for (int nb = 0; nb < 4; ++nb)
                LDSM4(bb[nb], sbB + bro[nb] + (((unsigned)chb ^ br7[nb]) << 4));
#pragma unroll
            for (int mi = 0; mi < 2; ++mi)
#pragma unroll
                for (int nb = 0; nb < 4; ++nb) {
                    MMA2(acc[mi][2*nb],   aa[mi], bb[nb][0], bb[nb][1]);
                    MMA2(acc[mi][2*nb+1], aa[mi], bb[nb][2], bb[nb][3]);
                }
        }

        if (++tap == 9) { tap = 0; ++k; tapoff = 0; }
        else tapoff += ((tap == 3 || tap == 6) ? 64 : 1);
    }

    // ---- epilogue
    const float nstrv = *nstr;
#pragma unroll
    for (int mi = 0; mi < 2; ++mi) {
#pragma unroll
        for (int half = 0; half < 2; ++half) {
            int m = wm * 32 + mi * 16 + (lane >> 2) + half * 8;
            int h = h0 + (m >> 6);
            int w = m & 63;
            float nz = noise[(n * HH + h) * WW + w] * nstrv;
            size_t base = ((size_t)((n * HH + h) * WW + w)) * OO + o0;
#pragma unroll
            for (int ni = 0; ni < 8; ++ni) {
                int oc = wn * 64 + ni * 8 + 2 * (lane & 3);
                float dm0 = g_dmul[n * OO + o0 + oc];
                float dm1 = g_dmul[n * OO + o0 + oc + 1];
                float b0 = bias[o0 + oc], b1 = bias[o0 + oc + 1];
                float y0 = fmaf(acc[mi][ni][half * 2],     dm0, nz + b0);
                float y1 = fmaf(acc[mi][ni][half * 2 + 1], dm1, nz + b1);
                y0 = (y0 > 0.f ? y0 : 0.2f * y0) * 1.4142135623730951f;
                y1 = (y1 > 0.f ? y1 : 0.2f * y1) * 1.4142135623730951f;
                *(float2*)(out + base + oc) = make_float2(y0, y1);
            }
        }
    }
}

// ---------------------------------------------------------------------------
extern "C" void kernel_launch(void* const* d_in, const int* in_sizes, int n_in,
                              void* d_out, int out_size)
{
    const float* x      = (const float*)d_in[0];
    const float* dlat   = (const float*)d_in[1];
    const float* sw     = (const float*)d_in[2];
    const float* sbv    = (const float*)d_in[3];
    const float* weight = (const float*)d_in[4];
    const float* bias   = (const float*)d_in[5];
    const float* nstr   = (const float*)d_in[6];
    const float* noise  = (const float*)d_in[7];
    const int*   lidx   = (const int*)  d_in[8];
    float* out = (float*)d_out;

    prep_a_kernel<<<NN + CC + 1152, 512>>>(dlat, sw, sbv, lidx, weight);
    prep_b_kernel<<<NN + 8192, 512>>>(x);

    cudaFuncSetAttribute(conv_mma_kernel,
                         cudaFuncAttributeMaxDynamicSharedMemorySize, SMEM_TOTAL);
    conv_mma_kernel<<<dim3(4, 512), 256, SMEM_TOTAL>>>(bias, nstr, noise, out);
}